// round 9
// baseline (speedup 1.0000x reference)
#include <cuda_runtime.h>
#include <cuda_fp16.h>
#include <cstdint>

#define BB   64
#define SS   1024
#define EE   128
#define HH   512
#define GG   2048
#define NTHR 256
#define NCR  64        // rnn CTAs
#define HPC  8         // h columns per CTA
#define MRR  32        // D rows per CTA = 4 gates x 8 h

// ---- rnn dynamic smem layout (bytes) ----
#define A_BYTES (MRR * HH * 2)           // 32768 fp16 W tile (row-swizzled)
#define B_BYTES (BB * HH * 2)            // 65536 fp16 H tile (row-swizzled)
#define G_OFF   (A_BYTES + B_BYTES)      // 98304: Gsm float[32][72]
#define G_BYTES (MRR * 72 * 4)           // 9216
#define HN_OFF  (G_OFF + G_BYTES)        // HnSm half[8][66]
#define HN_BYTES (8 * 66 * 2)
#define YS_OFF  (HN_OFF + HN_BYTES)      // Ysm float[8][72]
#define YS_BYTES (8 * 72 * 4)
#define RNN_SMEM (YS_OFF + YS_BYTES)

// ---------------- module-scope scratch ----------------
__device__ __align__(128) float         g_xg[(size_t)SS * GG * BB];   // [s][g*512+h][b]
__device__ __align__(128) __half        g_Hbuf[2][BB * HH];           // [b][h] fp16
__device__ __align__(128) float         g_Cbuf[HH * BB];              // [h][b]
__device__ __align__(128) float         g_Hfin[HH * BB];              // [h][b]
__device__ __align__(128) float         g_weff[HH];
__device__ __align__(128) float         g_beff[1];
__device__ __align__(128) float         g_party[(size_t)NCR * SS * BB];
__device__ __align__(128) unsigned      g_flagv[NCR * 32];            // 128B-strided arrival flags
__device__ __align__(128) unsigned      g_gov[32];                    // go word (own line)
__device__ __align__(128) unsigned char g_Abuf[(size_t)NCR * A_BYTES];   // rnn W images

__device__ __forceinline__ float sigf(float x)   { return 1.f / (1.f + __expf(-x)); }
__device__ __forceinline__ float tanhf_(float x) { return 2.f / (1.f + __expf(-2.f * x)) - 1.f; }

__device__ __forceinline__ uint32_t smem_u32(const void* p) {
    uint32_t a;
    asm("{ .reg .u64 t; cvta.to.shared.u64 t, %1; cvt.u32.u64 %0, t; }" : "=r"(a) : "l"(p));
    return a;
}
__device__ __forceinline__ void ldsm4(uint32_t* r, uint32_t addr) {
    asm volatile("ldmatrix.sync.aligned.m8n8.x4.shared.b16 {%0,%1,%2,%3}, [%4];"
                 : "=r"(r[0]), "=r"(r[1]), "=r"(r[2]), "=r"(r[3]) : "r"(addr));
}
__device__ __forceinline__ void mma16816(float* d, const uint32_t* a, const uint32_t* b) {
    asm volatile("mma.sync.aligned.m16n8k16.row.col.f32.f16.f16.f32 "
                 "{%0,%1,%2,%3}, {%4,%5,%6,%7}, {%8,%9}, {%0,%1,%2,%3};"
                 : "+f"(d[0]), "+f"(d[1]), "+f"(d[2]), "+f"(d[3])
                 : "r"(a[0]), "r"(a[1]), "r"(a[2]), "r"(a[3]), "r"(b[0]), "r"(b[1]));
}
__device__ __forceinline__ void st_release(unsigned* p, unsigned v) {
    asm volatile("st.release.gpu.global.u32 [%0], %1;" :: "l"(p), "r"(v) : "memory");
}
__device__ __forceinline__ unsigned ld_acquire(const unsigned* p) {
    unsigned v;
    asm volatile("ld.acquire.gpu.global.u32 %0, [%1];" : "=r"(v) : "l"(p) : "memory");
    return v;
}

// ---------------- init ----------------
__global__ void __launch_bounds__(NTHR) init_kernel(
    const float* __restrict__ H0, const float* __restrict__ C0,
    const float* __restrict__ Whq, const float* __restrict__ bq,
    const float* __restrict__ dw, const float* __restrict__ db)
{
    int t = blockIdx.x * blockDim.x + threadIdx.x;
    if (t < HH * BB) {
        int b = t >> 9, h = t & 511;
        g_Hbuf[0][t]       = __float2half_rn(H0[t]);   // [b][h]
        g_Cbuf[h * BB + b] = C0[t];
    }
    if (t < HH) {
        float a = 0.f;
        #pragma unroll 8
        for (int e = 0; e < EE; e++) a += Whq[t * EE + e] * dw[e];
        g_weff[t] = a;
    }
    if (t == 0) {
        float a = 0.f;
        for (int e = 0; e < EE; e++) a += bq[e] * dw[e];
        g_beff[0] = a + db[0];
    }
    if (t < NCR * 32) g_flagv[t] = 0u;
    if (t >= NCR * 32 && t < NCR * 32 + 32) g_gov[t - NCR * 32] = 0u;
}

// ---------------- prep: rnn W images (row-swizzled fp16) ---------------------
__global__ void __launch_bounds__(NTHR) prep_kernel(
    const float* __restrict__ Whi, const float* __restrict__ Whf,
    const float* __restrict__ Who, const float* __restrict__ Whc)
{
    int idx = blockIdx.x * blockDim.x + threadIdx.x;   // 64*32*512 = 1M
    int c = idx >> 14;
    int r = idx & 16383;
    int m = r >> 9;
    int k = r & 511;
    int g = m >> 3, u = m & 7;
    const float* W = (g == 0) ? Whi : (g == 1) ? Whf : (g == 2) ? Who : Whc;
    float v = W[(size_t)k * HH + c * HPC + u];
    uint32_t pos = (uint32_t)m * 1024 + (((uint32_t)k * 2) ^ (((uint32_t)m & 7) << 4));
    *(__half*)(g_Abuf + (size_t)c * A_BYTES + pos) = __float2half_rn(v);
}

// ---------------- phase 1: x-gate GEMMs (fp32, proven) -----------------------
__global__ void __launch_bounds__(NTHR) xg_kernel(
    const int* __restrict__ inputs, const float* __restrict__ emb,
    const float* __restrict__ Wxi, const float* __restrict__ Wxf,
    const float* __restrict__ Wxo, const float* __restrict__ Wxc,
    const float* __restrict__ bi,  const float* __restrict__ bf,
    const float* __restrict__ bo,  const float* __restrict__ bc)
{
    __shared__ __align__(16) float Xs[EE * BB];

    int blk   = blockIdx.x;
    int s     = blk >> 5;
    int cb    = blk & 31;
    int g     = cb >> 3;
    int colg0 = (cb & 7) * 64;
    const float* Wx   = (g == 0) ? Wxi : (g == 1) ? Wxf : (g == 2) ? Wxo : Wxc;
    const float* bias = (g == 0) ? bi  : (g == 1) ? bf  : (g == 2) ? bo  : bc;
    int t = threadIdx.x;

    {
        int b = t >> 2, part = t & 3;
        int tok = inputs[b * SS + s];
        const float4* src = (const float4*)(emb + (size_t)tok * EE) + part * 8;
        #pragma unroll
        for (int i = 0; i < 8; i++) {
            float4 v = src[i];
            int k = part * 32 + i * 4;
            Xs[(k + 0) * BB + b] = v.x;
            Xs[(k + 1) * BB + b] = v.y;
            Xs[(k + 2) * BB + b] = v.z;
            Xs[(k + 3) * BB + b] = v.w;
        }
    }
    __syncthreads();

    int cg = t & 15, bg = t >> 4;
    int b0 = bg * 4;
    const float* Wp = Wx + colg0 + cg * 4;
    float acc[4][4];
    #pragma unroll
    for (int i = 0; i < 4; i++) { acc[i][0]=0.f; acc[i][1]=0.f; acc[i][2]=0.f; acc[i][3]=0.f; }

    #pragma unroll 4
    for (int k = 0; k < EE; k++) {
        float4 wv = __ldg((const float4*)(Wp + (size_t)k * HH));
        float4 xv = *(const float4*)&Xs[k * BB + b0];
        float wa[4] = {wv.x, wv.y, wv.z, wv.w};
        float xa[4] = {xv.x, xv.y, xv.z, xv.w};
        #pragma unroll
        for (int i = 0; i < 4; i++)
            #pragma unroll
            for (int jj = 0; jj < 4; jj++)
                acc[i][jj] = fmaf(wa[i], xa[jj], acc[i][jj]);
    }

    size_t base = ((size_t)s * GG + (size_t)g * HH + colg0 + cg * 4) * BB;
    #pragma unroll
    for (int i = 0; i < 4; i++) {
        float bv = bias[colg0 + cg * 4 + i];
        float4 v = make_float4(acc[i][0] + bv, acc[i][1] + bv, acc[i][2] + bv, acc[i][3] + bv);
        *(float4*)&g_xg[base + (size_t)i * BB + b0] = v;
    }
}

// ---------------- phase 2: HMMA persistent recurrence, 64 CTAs ---------------
__global__ void __launch_bounds__(NTHR, 1) rnn_kernel()
{
    extern __shared__ __align__(16) unsigned char sm[];
    float*  Gsm  = (float*)(sm + G_OFF);
    __half* HnSm = (__half*)(sm + HN_OFF);
    float*  Ysm  = (float*)(sm + YS_OFF);
    const uint32_t smb = smem_u32(sm);
    const uint32_t Ab  = smb;
    const uint32_t Bb  = smb + A_BYTES;

    const int t = threadIdx.x, lane = t & 31, wid = t >> 5;
    const int cta = blockIdx.x, hbase = cta * HPC;

    // load prebuilt A image (32 KB)
    {
        const float4* asrc = (const float4*)(g_Abuf + (size_t)cta * A_BYTES);
        float4* adst = (float4*)sm;
        #pragma unroll
        for (int j = 0; j < 8; j++)
            adst[j * 256 + t] = __ldg(&asrc[j * 256 + t]);
    }

    // ldmatrix lane-address precompute
    const int q = lane >> 3, r8 = lane & 7;
    const int mt = wid & 1;
    const int np = wid >> 1;
    const int arow = mt * 16 + r8 + ((q & 1) << 3);
    const uint32_t acol = (uint32_t)(q >> 1) * 16;
    const uint32_t aBase = Ab + (uint32_t)arow * 1024;
    const uint32_t axor  = ((uint32_t)arow & 7) << 4;
    const int brow = np * 16 + r8 + ((q >> 1) << 3);
    const uint32_t bcol = (uint32_t)(q & 1) * 16;
    const uint32_t bBase = Bb + (uint32_t)brow * 1024;
    const uint32_t bxor  = ((uint32_t)brow & 7) << 4;

    // epilogue role
    const int u = wid, eb = lane;
    float C0r = g_Cbuf[(hbase + u) * BB + eb];
    float C1r = g_Cbuf[(hbase + u) * BB + eb + 32];
    const float wef = g_weff[hbase + u];
    __syncthreads();

    for (int step = 0; step < SS; step++) {
        // xg prefetch (8 scalar loads, coalesced; consumed after GEMM)
        size_t xb = ((size_t)step * GG + hbase + u) * BB + eb;
        float xi0 = __ldg(&g_xg[xb]),          xi1 = __ldg(&g_xg[xb + 32]);
        float xf0 = __ldg(&g_xg[xb + 32768]),  xf1 = __ldg(&g_xg[xb + 32768 + 32]);
        float xo0 = __ldg(&g_xg[xb + 65536]),  xo1 = __ldg(&g_xg[xb + 65536 + 32]);
        float xc0 = __ldg(&g_xg[xb + 98304]),  xc1 = __ldg(&g_xg[xb + 98304 + 32]);

        // stage H [b][h] fp16 -> Bsm, per-row XOR swizzle
        {
            const float4* hs = (const float4*)g_Hbuf[step & 1];
            #pragma unroll
            for (int j = 0; j < 16; j++) {
                int i16 = j * 256 + t;
                float4 v = __ldcg(&hs[i16]);
                uint32_t b   = (uint32_t)i16 >> 6;
                uint32_t c16 = (uint32_t)i16 & 63;
                *(float4*)(sm + A_BYTES + b * 1024 + ((c16 * 16) ^ ((b & 7) << 4))) = v;
            }
        }
        __syncthreads();

        // GEMM: per warp 32 k-slices, 2 ntiles
        float d0[4] = {0.f, 0.f, 0.f, 0.f};
        float d1[4] = {0.f, 0.f, 0.f, 0.f};
        #pragma unroll 8
        for (int ks = 0; ks < 32; ks++) {
            uint32_t a[4], b2[4];
            ldsm4(a,  aBase + (((uint32_t)ks * 32 + acol) ^ axor));
            ldsm4(b2, bBase + (((uint32_t)ks * 32 + bcol) ^ bxor));
            mma16816(d0, a, b2);
            mma16816(d1, a, b2 + 2);
        }
        {
            int g4 = lane >> 2, t4 = lane & 3;
            int mrow = mt * 16 + g4, nc = np * 16 + 2 * t4;
            *(float2*)&Gsm[mrow * 72 + nc]           = make_float2(d0[0], d0[1]);
            *(float2*)&Gsm[(mrow + 8) * 72 + nc]     = make_float2(d0[2], d0[3]);
            *(float2*)&Gsm[mrow * 72 + nc + 8]       = make_float2(d1[0], d1[1]);
            *(float2*)&Gsm[(mrow + 8) * 72 + nc + 8] = make_float2(d1[2], d1[3]);
        }
        __syncthreads();

        // epilogue: 2 cells per thread
        {
            float pi = xi0 + Gsm[( 0 + u) * 72 + eb];
            float pf = xf0 + Gsm[( 8 + u) * 72 + eb];
            float po = xo0 + Gsm[(16 + u) * 72 + eb];
            float pc = xc0 + Gsm[(24 + u) * 72 + eb];
            float I = sigf(pi), F = sigf(pf), O = sigf(po), Ct = tanhf_(pc);
            C0r = F * C0r + I * Ct;
            float Hn = O * tanhf_(C0r);
            HnSm[u * 66 + eb] = __float2half_rn(Hn);
            Ysm[u * 72 + eb]  = Hn * wef;
            if (step == SS - 1) { g_Hfin[(hbase + u) * BB + eb] = Hn; g_Cbuf[(hbase + u) * BB + eb] = C0r; }
        }
        {
            int bb = eb + 32;
            float pi = xi1 + Gsm[( 0 + u) * 72 + bb];
            float pf = xf1 + Gsm[( 8 + u) * 72 + bb];
            float po = xo1 + Gsm[(16 + u) * 72 + bb];
            float pc = xc1 + Gsm[(24 + u) * 72 + bb];
            float I = sigf(pi), F = sigf(pf), O = sigf(po), Ct = tanhf_(pc);
            C1r = F * C1r + I * Ct;
            float Hn = O * tanhf_(C1r);
            HnSm[u * 66 + bb] = __float2half_rn(Hn);
            Ysm[u * 72 + bb]  = Hn * wef;
            if (step == SS - 1) { g_Hfin[(hbase + u) * BB + bb] = Hn; g_Cbuf[(hbase + u) * BB + bb] = C1r; }
        }
        __syncthreads();

        // pack new H (coalesced 16B per batch) + Y partial
        if (t < BB) {
            uint32_t p[4];
            #pragma unroll
            for (int uu = 0; uu < 4; uu++) {
                uint32_t lo = (uint32_t)__half_as_ushort(HnSm[(2 * uu)     * 66 + t]);
                uint32_t hi = (uint32_t)__half_as_ushort(HnSm[(2 * uu + 1) * 66 + t]);
                p[uu] = lo | (hi << 16);
            }
            *(uint4*)((unsigned char*)g_Hbuf[(step + 1) & 1] + (size_t)t * 1024 + (size_t)cta * 16)
                = make_uint4(p[0], p[1], p[2], p[3]);
        } else if (t < 2 * BB) {
            int bb = t - BB;
            float y = 0.f;
            #pragma unroll
            for (int uu = 0; uu < 8; uu++) y += Ysm[uu * 72 + bb];
            g_party[((size_t)cta * SS + step) * BB + bb] = y;
        }

        // ---- 64-CTA flag barrier: release-stores to distinct lines, no atomics ----
        __threadfence();
        __syncthreads();
        const unsigned sv = (unsigned)step + 1u;
        if (cta == 0) {
            // 63 threads acquire-poll the arrival flags in parallel
            if (t > 0 && t < NCR) {
                while (ld_acquire(&g_flagv[t * 32]) < sv) { }
            }
            __syncthreads();
            if (t == 0) {
                st_release(&g_gov[0], sv);
                __threadfence();
            }
        } else {
            if (t == 0) {
                st_release(&g_flagv[cta * 32], sv);
                while (ld_acquire(&g_gov[0]) < sv) { }
                __threadfence();
            }
        }
        __syncthreads();
    }
}

// ---------------- finalize ----------------------------------------------------
__global__ void __launch_bounds__(NTHR) fin_kernel(float* __restrict__ out, int out_size)
{
    int blk = blockIdx.x, t = threadIdx.x;
    if (blk < SS) {
        if (t < BB) {
            float y = g_beff[0];
            #pragma unroll
            for (int c = 0; c < NCR; c++)
                y += g_party[((size_t)c * SS + blk) * BB + t];
            int o = blk * BB + t;
            if (o < out_size) out[o] = y;
        }
    } else {
        if (out_size < SS * BB + 2 * HH * BB) return;
        int i = (blk - SS) * NTHR + t;
        if (i < HH * BB) {
            int h = i >> 6, b = i & 63;
            out[SS * BB + b * HH + h] = g_Hfin[i];
        } else {
            int j = i - HH * BB;
            int h = j >> 6, b = j & 63;
            out[SS * BB + HH * BB + b * HH + h] = g_Cbuf[j];
        }
    }
}

// ---------------- launch ------------------------------------------------------
extern "C" void kernel_launch(void* const* d_in, const int* in_sizes, int n_in,
                              void* d_out, int out_size)
{
    const int*   inputs = (const int*)d_in[0];
    const float* H0  = (const float*)d_in[1];
    const float* C0  = (const float*)d_in[2];
    const float* emb = (const float*)d_in[3];
    const float* Wxi = (const float*)d_in[4];
    const float* Whi = (const float*)d_in[5];
    const float* bi  = (const float*)d_in[6];
    const float* Wxf = (const float*)d_in[7];
    const float* Whf = (const float*)d_in[8];
    const float* bf  = (const float*)d_in[9];
    const float* Wxo = (const float*)d_in[10];
    const float* Who = (const float*)d_in[11];
    const float* bo  = (const float*)d_in[12];
    const float* Wxc = (const float*)d_in[13];
    const float* Whc = (const float*)d_in[14];
    const float* bc  = (const float*)d_in[15];
    const float* Whq = (const float*)d_in[16];
    const float* bq  = (const float*)d_in[17];
    const float* dw  = (const float*)d_in[18];
    const float* db  = (const float*)d_in[19];
    float* out = (float*)d_out;

    cudaFuncSetAttribute(rnn_kernel, cudaFuncAttributeMaxDynamicSharedMemorySize, RNN_SMEM);

    init_kernel<<<128, NTHR>>>(H0, C0, Whq, bq, dw, db);
    prep_kernel<<<(NCR * MRR * HH) / NTHR, NTHR>>>(Whi, Whf, Who, Whc);
    xg_kernel<<<SS * 32, NTHR>>>(inputs, emb, Wxi, Wxf, Wxo, Wxc, bi, bf, bo, bc);
    rnn_kernel<<<NCR, NTHR, RNN_SMEM>>>();
    fin_kernel<<<SS + (2 * HH * BB) / NTHR, NTHR>>>(out, out_size);
}

// round 10
// speedup vs baseline: 1.1894x; 1.1894x over previous
#include <cuda_runtime.h>
#include <cuda_fp16.h>
#include <cstdint>

#define BB   64
#define SS   1024
#define EE   128
#define HH   512
#define GG   2048
#define NTHR 256
#define NCR  64        // rnn consumer CTAs
#define NPR  64        // xg producer CTAs
#define HPC  8         // h columns per CTA
#define MRR  32        // D rows per CTA = 4 gates x 8 h

// ---- rnn dynamic smem layout (bytes) ----
#define A_BYTES (MRR * HH * 2)           // 32768 fp16 W tile (row-swizzled)
#define B_BYTES (BB * HH * 2)            // 65536 fp16 H tile (row-swizzled)
#define G_OFF   (A_BYTES + B_BYTES)      // 98304: Gsm float[32][72]
#define G_BYTES (MRR * 72 * 4)           // 9216
#define HN_OFF  (G_OFF + G_BYTES)        // HnSm half[8][66]
#define HN_BYTES (8 * 66 * 2)
#define YS_OFF  (HN_OFF + HN_BYTES)      // Ysm float[8][72]
#define YS_BYTES (8 * 72 * 4)
#define RNN_SMEM (YS_OFF + YS_BYTES)     // 110880 (producer path reuses [0,32KB) as Xs)

// ---------------- module-scope scratch ----------------
__device__ __align__(128) float         g_xg[(size_t)SS * GG * BB];   // [s][g*512+h][b]
__device__ __align__(128) __half        g_Hbuf[2][BB * HH];           // [b][h] fp16
__device__ __align__(128) float         g_Cbuf[HH * BB];              // [h][b]
__device__ __align__(128) float         g_Hfin[HH * BB];              // [h][b]
__device__ __align__(128) float         g_weff[HH];
__device__ __align__(128) float         g_beff[1];
__device__ __align__(128) float         g_party[(size_t)NCR * SS * BB];
__device__ __align__(128) unsigned      g_flagv[NCR * 32];            // 128B-strided step flags
__device__ __align__(128) unsigned      g_xgcnt[32];                  // per-32-step xg block counts
__device__ __align__(128) unsigned char g_Abuf[(size_t)NCR * A_BYTES];   // rnn W images

__device__ __forceinline__ float sigf(float x)   { return 1.f / (1.f + __expf(-x)); }
__device__ __forceinline__ float tanhf_(float x) { return 2.f / (1.f + __expf(-2.f * x)) - 1.f; }

__device__ __forceinline__ uint32_t smem_u32(const void* p) {
    uint32_t a;
    asm("{ .reg .u64 t; cvta.to.shared.u64 t, %1; cvt.u32.u64 %0, t; }" : "=r"(a) : "l"(p));
    return a;
}
__device__ __forceinline__ void ldsm4(uint32_t* r, uint32_t addr) {
    asm volatile("ldmatrix.sync.aligned.m8n8.x4.shared.b16 {%0,%1,%2,%3}, [%4];"
                 : "=r"(r[0]), "=r"(r[1]), "=r"(r[2]), "=r"(r[3]) : "r"(addr));
}
__device__ __forceinline__ void mma16816(float* d, const uint32_t* a, const uint32_t* b) {
    asm volatile("mma.sync.aligned.m16n8k16.row.col.f32.f16.f16.f32 "
                 "{%0,%1,%2,%3}, {%4,%5,%6,%7}, {%8,%9}, {%0,%1,%2,%3};"
                 : "+f"(d[0]), "+f"(d[1]), "+f"(d[2]), "+f"(d[3])
                 : "r"(a[0]), "r"(a[1]), "r"(a[2]), "r"(a[3]), "r"(b[0]), "r"(b[1]));
}
__device__ __forceinline__ void st_release(unsigned* p, unsigned v) {
    asm volatile("st.release.gpu.global.u32 [%0], %1;" :: "l"(p), "r"(v) : "memory");
}
__device__ __forceinline__ unsigned ld_acquire(const unsigned* p) {
    unsigned v;
    asm volatile("ld.acquire.gpu.global.u32 %0, [%1];" : "=r"(v) : "l"(p) : "memory");
    return v;
}
__device__ __forceinline__ void red_release_add(unsigned* p, unsigned v) {
    asm volatile("red.release.gpu.global.add.u32 [%0], %1;" :: "l"(p), "r"(v) : "memory");
}

// ---------------- init ----------------
__global__ void __launch_bounds__(NTHR) init_kernel(
    const float* __restrict__ H0, const float* __restrict__ C0,
    const float* __restrict__ Whq, const float* __restrict__ bq,
    const float* __restrict__ dw, const float* __restrict__ db)
{
    int t = blockIdx.x * blockDim.x + threadIdx.x;
    if (t < HH * BB) {
        int b = t >> 9, h = t & 511;
        g_Hbuf[0][t]       = __float2half_rn(H0[t]);   // [b][h]
        g_Cbuf[h * BB + b] = C0[t];
    }
    if (t < HH) {
        float a = 0.f;
        #pragma unroll 8
        for (int e = 0; e < EE; e++) a += Whq[t * EE + e] * dw[e];
        g_weff[t] = a;
    }
    if (t == 0) {
        float a = 0.f;
        for (int e = 0; e < EE; e++) a += bq[e] * dw[e];
        g_beff[0] = a + db[0];
    }
    if (t < NCR * 32) g_flagv[t] = 0u;
    if (t >= NCR * 32 && t < NCR * 32 + 32) g_xgcnt[t - NCR * 32] = 0u;
}

// ---------------- prep: rnn W images (row-swizzled fp16) ---------------------
__global__ void __launch_bounds__(NTHR) prep_kernel(
    const float* __restrict__ Whi, const float* __restrict__ Whf,
    const float* __restrict__ Who, const float* __restrict__ Whc)
{
    int idx = blockIdx.x * blockDim.x + threadIdx.x;   // 64*32*512 = 1M
    int c = idx >> 14;
    int r = idx & 16383;
    int m = r >> 9;
    int k = r & 511;
    int g = m >> 3, u = m & 7;
    const float* W = (g == 0) ? Whi : (g == 1) ? Whf : (g == 2) ? Who : Whc;
    float v = W[(size_t)k * HH + c * HPC + u];
    uint32_t pos = (uint32_t)m * 1024 + (((uint32_t)k * 2) ^ (((uint32_t)m & 7) << 4));
    *(__half*)(g_Abuf + (size_t)c * A_BYTES + pos) = __float2half_rn(v);
}

// ---------------- fused kernel: consumers (CTA 0-63) + xg producers (64-127) --
__global__ void __launch_bounds__(NTHR, 1) rnn_kernel(
    const int* __restrict__ inputs, const float* __restrict__ emb,
    const float* __restrict__ Wxi, const float* __restrict__ Wxf,
    const float* __restrict__ Wxo, const float* __restrict__ Wxc,
    const float* __restrict__ bi,  const float* __restrict__ bf,
    const float* __restrict__ bo,  const float* __restrict__ bc)
{
    extern __shared__ __align__(16) unsigned char sm[];
    const int t = threadIdx.x, lane = t & 31, wid = t >> 5;
    const int cta = blockIdx.x;

    if (cta >= NCR) {
        // ================= producer path: verbatim R5 xg math, chunk loop ====
        float* Xs = (float*)sm;                 // [k][b] 32KB
        const int p = cta - NCR;
        for (int i = 0; i < 512; i++) {
            int chunk = p + (i << 6);           // s strictly non-decreasing in i
            int s     = chunk >> 5;
            int cb    = chunk & 31;
            int g     = cb >> 3;
            int colg0 = (cb & 7) * 64;
            const float* Wx   = (g == 0) ? Wxi : (g == 1) ? Wxf : (g == 2) ? Wxo : Wxc;
            const float* bias = (g == 0) ? bi  : (g == 1) ? bf  : (g == 2) ? bo  : bc;

            {
                int b = t >> 2, part = t & 3;
                int tok = inputs[b * SS + s];
                const float4* src = (const float4*)(emb + (size_t)tok * EE) + part * 8;
                #pragma unroll
                for (int j = 0; j < 8; j++) {
                    float4 v = src[j];
                    int k = part * 32 + j * 4;
                    Xs[(k + 0) * BB + b] = v.x;
                    Xs[(k + 1) * BB + b] = v.y;
                    Xs[(k + 2) * BB + b] = v.z;
                    Xs[(k + 3) * BB + b] = v.w;
                }
            }
            __syncthreads();

            int cg = t & 15, bg = t >> 4;
            int b0 = bg * 4;
            const float* Wp = Wx + colg0 + cg * 4;
            float acc[4][4];
            #pragma unroll
            for (int j = 0; j < 4; j++) { acc[j][0]=0.f; acc[j][1]=0.f; acc[j][2]=0.f; acc[j][3]=0.f; }

            #pragma unroll 4
            for (int k = 0; k < EE; k++) {
                float4 wv = __ldg((const float4*)(Wp + (size_t)k * HH));
                float4 xv = *(const float4*)&Xs[k * BB + b0];
                float wa[4] = {wv.x, wv.y, wv.z, wv.w};
                float xa[4] = {xv.x, xv.y, xv.z, xv.w};
                #pragma unroll
                for (int j = 0; j < 4; j++)
                    #pragma unroll
                    for (int jj = 0; jj < 4; jj++)
                        acc[j][jj] = fmaf(wa[j], xa[jj], acc[j][jj]);
            }

            size_t base = ((size_t)s * GG + (size_t)g * HH + colg0 + cg * 4) * BB;
            #pragma unroll
            for (int j = 0; j < 4; j++) {
                float bv = bias[colg0 + cg * 4 + j];
                float4 v = make_float4(acc[j][0] + bv, acc[j][1] + bv, acc[j][2] + bv, acc[j][3] + bv);
                *(float4*)&g_xg[base + (size_t)j * BB + b0] = v;
            }

            __threadfence();
            __syncthreads();
            if (t == 0) red_release_add(&g_xgcnt[s >> 5], 1u);   // 1024 per 32-s block
        }
        return;
    }

    // ================= consumer path: R5-exact recurrence, barrier v3 ========
    float*  Gsm  = (float*)(sm + G_OFF);
    __half* HnSm = (__half*)(sm + HN_OFF);
    float*  Ysm  = (float*)(sm + YS_OFF);
    const uint32_t smb = smem_u32(sm);
    const uint32_t Ab  = smb;
    const uint32_t Bb  = smb + A_BYTES;
    const int hbase = cta * HPC;

    // load prebuilt A image (32 KB)
    {
        const float4* asrc = (const float4*)(g_Abuf + (size_t)cta * A_BYTES);
        float4* adst = (float4*)sm;
        #pragma unroll
        for (int j = 0; j < 8; j++)
            adst[j * 256 + t] = __ldg(&asrc[j * 256 + t]);
    }

    // ldmatrix lane-address precompute
    const int q = lane >> 3, r8 = lane & 7;
    const int mt = wid & 1;
    const int np = wid >> 1;
    const int arow = mt * 16 + r8 + ((q & 1) << 3);
    const uint32_t acol = (uint32_t)(q >> 1) * 16;
    const uint32_t aBase = Ab + (uint32_t)arow * 1024;
    const uint32_t axor  = ((uint32_t)arow & 7) << 4;
    const int brow = np * 16 + r8 + ((q >> 1) << 3);
    const uint32_t bcol = (uint32_t)(q & 1) * 16;
    const uint32_t bBase = Bb + (uint32_t)brow * 1024;
    const uint32_t bxor  = ((uint32_t)brow & 7) << 4;

    // epilogue role
    const int u = wid, eb = lane;
    float C0r = g_Cbuf[(hbase + u) * BB + eb];
    float C1r = g_Cbuf[(hbase + u) * BB + eb + 32];
    const float wef = g_weff[hbase + u];
    __syncthreads();

    for (int step = 0; step < SS; step++) {
        // wait for producers to finish this 32-step xg block (amortized)
        if ((step & 31) == 0) {
            if (t == 0) {
                while (ld_acquire(&g_xgcnt[step >> 5]) < 1024u) { }
            }
            __syncthreads();
        }

        // xg prefetch (8 scalar loads, coalesced; consumed after GEMM)
        size_t xb = ((size_t)step * GG + hbase + u) * BB + eb;
        float xi0 = __ldg(&g_xg[xb]),          xi1 = __ldg(&g_xg[xb + 32]);
        float xf0 = __ldg(&g_xg[xb + 32768]),  xf1 = __ldg(&g_xg[xb + 32768 + 32]);
        float xo0 = __ldg(&g_xg[xb + 65536]),  xo1 = __ldg(&g_xg[xb + 65536 + 32]);
        float xc0 = __ldg(&g_xg[xb + 98304]),  xc1 = __ldg(&g_xg[xb + 98304 + 32]);

        // stage H [b][h] fp16 -> Bsm, per-row XOR swizzle
        {
            const float4* hs = (const float4*)g_Hbuf[step & 1];
            #pragma unroll
            for (int j = 0; j < 16; j++) {
                int i16 = j * 256 + t;
                float4 v = __ldcg(&hs[i16]);
                uint32_t b   = (uint32_t)i16 >> 6;
                uint32_t c16 = (uint32_t)i16 & 63;
                *(float4*)(sm + A_BYTES + b * 1024 + ((c16 * 16) ^ ((b & 7) << 4))) = v;
            }
        }
        __syncthreads();

        // GEMM: per warp 32 k-slices, 2 ntiles
        float d0[4] = {0.f, 0.f, 0.f, 0.f};
        float d1[4] = {0.f, 0.f, 0.f, 0.f};
        #pragma unroll 8
        for (int ks = 0; ks < 32; ks++) {
            uint32_t a[4], b2[4];
            ldsm4(a,  aBase + (((uint32_t)ks * 32 + acol) ^ axor));
            ldsm4(b2, bBase + (((uint32_t)ks * 32 + bcol) ^ bxor));
            mma16816(d0, a, b2);
            mma16816(d1, a, b2 + 2);
        }
        {
            int g4 = lane >> 2, t4 = lane & 3;
            int mrow = mt * 16 + g4, nc = np * 16 + 2 * t4;
            *(float2*)&Gsm[mrow * 72 + nc]           = make_float2(d0[0], d0[1]);
            *(float2*)&Gsm[(mrow + 8) * 72 + nc]     = make_float2(d0[2], d0[3]);
            *(float2*)&Gsm[mrow * 72 + nc + 8]       = make_float2(d1[0], d1[1]);
            *(float2*)&Gsm[(mrow + 8) * 72 + nc + 8] = make_float2(d1[2], d1[3]);
        }
        __syncthreads();

        // epilogue: 2 cells per thread
        {
            float pi = xi0 + Gsm[( 0 + u) * 72 + eb];
            float pf = xf0 + Gsm[( 8 + u) * 72 + eb];
            float po = xo0 + Gsm[(16 + u) * 72 + eb];
            float pc = xc0 + Gsm[(24 + u) * 72 + eb];
            float I = sigf(pi), F = sigf(pf), O = sigf(po), Ct = tanhf_(pc);
            C0r = F * C0r + I * Ct;
            float Hn = O * tanhf_(C0r);
            HnSm[u * 66 + eb] = __float2half_rn(Hn);
            Ysm[u * 72 + eb]  = Hn * wef;
            if (step == SS - 1) { g_Hfin[(hbase + u) * BB + eb] = Hn; g_Cbuf[(hbase + u) * BB + eb] = C0r; }
        }
        {
            int bb = eb + 32;
            float pi = xi1 + Gsm[( 0 + u) * 72 + bb];
            float pf = xf1 + Gsm[( 8 + u) * 72 + bb];
            float po = xo1 + Gsm[(16 + u) * 72 + bb];
            float pc = xc1 + Gsm[(24 + u) * 72 + bb];
            float I = sigf(pi), F = sigf(pf), O = sigf(po), Ct = tanhf_(pc);
            C1r = F * C1r + I * Ct;
            float Hn = O * tanhf_(C1r);
            HnSm[u * 66 + bb] = __float2half_rn(Hn);
            Ysm[u * 72 + bb]  = Hn * wef;
            if (step == SS - 1) { g_Hfin[(hbase + u) * BB + bb] = Hn; g_Cbuf[(hbase + u) * BB + bb] = C1r; }
        }
        __syncthreads();

        // pack new H (coalesced 16B per batch) + Y partial
        if (t < BB) {
            uint32_t p[4];
            #pragma unroll
            for (int uu = 0; uu < 4; uu++) {
                uint32_t lo = (uint32_t)__half_as_ushort(HnSm[(2 * uu)     * 66 + t]);
                uint32_t hi = (uint32_t)__half_as_ushort(HnSm[(2 * uu + 1) * 66 + t]);
                p[uu] = lo | (hi << 16);
            }
            *(uint4*)((unsigned char*)g_Hbuf[(step + 1) & 1] + (size_t)t * 1024 + (size_t)cta * 16)
                = make_uint4(p[0], p[1], p[2], p[3]);
        } else if (t < 2 * BB) {
            int bb = t - BB;
            float y = 0.f;
            #pragma unroll
            for (int uu = 0; uu < 8; uu++) y += Ysm[uu * 72 + bb];
            g_party[((size_t)cta * SS + step) * BB + bb] = y;
        }

        // ---- barrier v3: one-hop all-to-all, monotonic flags, no RMW ----
        __threadfence();
        __syncthreads();
        const unsigned sv = (unsigned)step + 1u;
        if (t == 0) st_release(&g_flagv[cta * 32], sv);
        if (t < NCR) {
            while (ld_acquire(&g_flagv[t * 32]) < sv) { }
        }
        __syncthreads();
    }
}

// ---------------- finalize ----------------------------------------------------
__global__ void __launch_bounds__(NTHR) fin_kernel(float* __restrict__ out, int out_size)
{
    int blk = blockIdx.x, t = threadIdx.x;
    if (blk < SS) {
        if (t < BB) {
            float y = g_beff[0];
            #pragma unroll
            for (int c = 0; c < NCR; c++)
                y += g_party[((size_t)c * SS + blk) * BB + t];
            int o = blk * BB + t;
            if (o < out_size) out[o] = y;
        }
    } else {
        if (out_size < SS * BB + 2 * HH * BB) return;
        int i = (blk - SS) * NTHR + t;
        if (i < HH * BB) {
            int h = i >> 6, b = i & 63;
            out[SS * BB + b * HH + h] = g_Hfin[i];
        } else {
            int j = i - HH * BB;
            int h = j >> 6, b = j & 63;
            out[SS * BB + HH * BB + b * HH + h] = g_Cbuf[j];
        }
    }
}

// ---------------- launch ------------------------------------------------------
extern "C" void kernel_launch(void* const* d_in, const int* in_sizes, int n_in,
                              void* d_out, int out_size)
{
    const int*   inputs = (const int*)d_in[0];
    const float* H0  = (const float*)d_in[1];
    const float* C0  = (const float*)d_in[2];
    const float* emb = (const float*)d_in[3];
    const float* Wxi = (const float*)d_in[4];
    const float* Whi = (const float*)d_in[5];
    const float* bi  = (const float*)d_in[6];
    const float* Wxf = (const float*)d_in[7];
    const float* Whf = (const float*)d_in[8];
    const float* bf  = (const float*)d_in[9];
    const float* Wxo = (const float*)d_in[10];
    const float* Who = (const float*)d_in[11];
    const float* bo  = (const float*)d_in[12];
    const float* Wxc = (const float*)d_in[13];
    const float* Whc = (const float*)d_in[14];
    const float* bc  = (const float*)d_in[15];
    const float* Whq = (const float*)d_in[16];
    const float* bq  = (const float*)d_in[17];
    const float* dw  = (const float*)d_in[18];
    const float* db  = (const float*)d_in[19];
    float* out = (float*)d_out;

    cudaFuncSetAttribute(rnn_kernel, cudaFuncAttributeMaxDynamicSharedMemorySize, RNN_SMEM);

    init_kernel<<<128, NTHR>>>(H0, C0, Whq, bq, dw, db);
    prep_kernel<<<(NCR * MRR * HH) / NTHR, NTHR>>>(Whi, Whf, Who, Whc);
    rnn_kernel<<<NCR + NPR, NTHR, RNN_SMEM>>>(inputs, emb,
                                              Wxi, Wxf, Wxo, Wxc, bi, bf, bo, bc);
    fin_kernel<<<SS + (2 * HH * BB) / NTHR, NTHR>>>(out, out_size);
}

// round 11
// speedup vs baseline: 1.1954x; 1.0050x over previous
#include <cuda_runtime.h>
#include <cuda_fp16.h>
#include <cstdint>

#define BB   64
#define SS   1024
#define EE   128
#define HH   512
#define GG   2048
#define NTHR 256
#define NCR  64        // rnn consumer CTAs
#define NPR  64        // xg producer CTAs
#define HPC  8         // h columns per CTA
#define MRR  32        // D rows per CTA = 4 gates x 8 h

// ---- rnn dynamic smem layout (bytes) ----
#define A_BYTES (MRR * HH * 2)           // 32768 fp16 W tile (row-swizzled)
#define B_BYTES (BB * HH * 2)            // 65536 fp16 H tile (row-swizzled)
#define G_OFF   (A_BYTES + B_BYTES)      // 98304: Gsm float[32][72]
#define G_BYTES (MRR * 72 * 4)           // 9216
#define HN_OFF  (G_OFF + G_BYTES)        // HnSm half[8][66]
#define HN_BYTES (8 * 66 * 2)
#define YS_OFF  (HN_OFF + HN_BYTES)      // Ysm float[8][72]
#define YS_BYTES (8 * 72 * 4)
#define RNN_SMEM (YS_OFF + YS_BYTES)     // 110880 (producer path reuses [0,32KB) as Xs)

// ---------------- module-scope scratch ----------------
__device__ __align__(128) float         g_xg[(size_t)SS * GG * BB];   // [s][g*512+h][b]
__device__ __align__(128) __half        g_Hbuf[2][BB * HH];           // [b][h] fp16
__device__ __align__(128) float         g_Cbuf[HH * BB];              // [h][b]
__device__ __align__(128) float         g_Hfin[HH * BB];              // [h][b]
__device__ __align__(128) float         g_weff[HH];
__device__ __align__(128) float         g_beff[1];
__device__ __align__(128) float         g_party[(size_t)NCR * SS * BB];
__device__ __align__(128) unsigned      g_bar[SS];                    // step arrival counters
__device__ __align__(128) unsigned      g_xgcnt[32];                  // per-32-step xg block counts
__device__ __align__(128) unsigned char g_Abuf[(size_t)NCR * A_BYTES];   // rnn W images

__device__ __forceinline__ float sigf(float x)   { return 1.f / (1.f + __expf(-x)); }
__device__ __forceinline__ float tanhf_(float x) { return 2.f / (1.f + __expf(-2.f * x)) - 1.f; }

__device__ __forceinline__ uint32_t smem_u32(const void* p) {
    uint32_t a;
    asm("{ .reg .u64 t; cvta.to.shared.u64 t, %1; cvt.u32.u64 %0, t; }" : "=r"(a) : "l"(p));
    return a;
}
__device__ __forceinline__ void ldsm4(uint32_t* r, uint32_t addr) {
    asm volatile("ldmatrix.sync.aligned.m8n8.x4.shared.b16 {%0,%1,%2,%3}, [%4];"
                 : "=r"(r[0]), "=r"(r[1]), "=r"(r[2]), "=r"(r[3]) : "r"(addr));
}
__device__ __forceinline__ void mma16816(float* d, const uint32_t* a, const uint32_t* b) {
    asm volatile("mma.sync.aligned.m16n8k16.row.col.f32.f16.f16.f32 "
                 "{%0,%1,%2,%3}, {%4,%5,%6,%7}, {%8,%9}, {%0,%1,%2,%3};"
                 : "+f"(d[0]), "+f"(d[1]), "+f"(d[2]), "+f"(d[3])
                 : "r"(a[0]), "r"(a[1]), "r"(a[2]), "r"(a[3]), "r"(b[0]), "r"(b[1]));
}
__device__ __forceinline__ unsigned ld_acquire(const unsigned* p) {
    unsigned v;
    asm volatile("ld.acquire.gpu.global.u32 %0, [%1];" : "=r"(v) : "l"(p) : "memory");
    return v;
}
__device__ __forceinline__ void red_release_add(unsigned* p, unsigned v) {
    asm volatile("red.release.gpu.global.add.u32 [%0], %1;" :: "l"(p), "r"(v) : "memory");
}

// ---------------- init ----------------
__global__ void __launch_bounds__(NTHR) init_kernel(
    const float* __restrict__ H0, const float* __restrict__ C0,
    const float* __restrict__ Whq, const float* __restrict__ bq,
    const float* __restrict__ dw, const float* __restrict__ db)
{
    int t = blockIdx.x * blockDim.x + threadIdx.x;
    if (t < HH * BB) {
        int b = t >> 9, h = t & 511;
        g_Hbuf[0][t]       = __float2half_rn(H0[t]);   // [b][h]
        g_Cbuf[h * BB + b] = C0[t];
    }
    if (t < HH) {
        float a = 0.f;
        #pragma unroll 8
        for (int e = 0; e < EE; e++) a += Whq[t * EE + e] * dw[e];
        g_weff[t] = a;
    }
    if (t == 0) {
        float a = 0.f;
        for (int e = 0; e < EE; e++) a += bq[e] * dw[e];
        g_beff[0] = a + db[0];
    }
    if (t < SS) g_bar[t] = 0u;
    if (t >= SS && t < SS + 32) g_xgcnt[t - SS] = 0u;
}

// ---------------- prep: rnn W images (row-swizzled fp16) ---------------------
__global__ void __launch_bounds__(NTHR) prep_kernel(
    const float* __restrict__ Whi, const float* __restrict__ Whf,
    const float* __restrict__ Who, const float* __restrict__ Whc)
{
    int idx = blockIdx.x * blockDim.x + threadIdx.x;   // 64*32*512 = 1M
    int c = idx >> 14;
    int r = idx & 16383;
    int m = r >> 9;
    int k = r & 511;
    int g = m >> 3, u = m & 7;
    const float* W = (g == 0) ? Whi : (g == 1) ? Whf : (g == 2) ? Who : Whc;
    float v = W[(size_t)k * HH + c * HPC + u];
    uint32_t pos = (uint32_t)m * 1024 + (((uint32_t)k * 2) ^ (((uint32_t)m & 7) << 4));
    *(__half*)(g_Abuf + (size_t)c * A_BYTES + pos) = __float2half_rn(v);
}

// ---------------- fused kernel: consumers (CTA 0-63) + xg producers (64-127) --
__global__ void __launch_bounds__(NTHR, 1) rnn_kernel(
    const int* __restrict__ inputs, const float* __restrict__ emb,
    const float* __restrict__ Wxi, const float* __restrict__ Wxf,
    const float* __restrict__ Wxo, const float* __restrict__ Wxc,
    const float* __restrict__ bi,  const float* __restrict__ bf,
    const float* __restrict__ bo,  const float* __restrict__ bc)
{
    extern __shared__ __align__(16) unsigned char sm[];
    const int t = threadIdx.x, lane = t & 31, wid = t >> 5;
    const int cta = blockIdx.x;

    if (cta >= NCR) {
        // ================= producer path: verbatim R5 xg math, chunk loop ====
        float* Xs = (float*)sm;                 // [k][b] 32KB
        const int p = cta - NCR;
        for (int i = 0; i < 512; i++) {
            int chunk = p + (i << 6);           // s strictly non-decreasing in i
            int s     = chunk >> 5;
            int cb    = chunk & 31;
            int g     = cb >> 3;
            int colg0 = (cb & 7) * 64;
            const float* Wx   = (g == 0) ? Wxi : (g == 1) ? Wxf : (g == 2) ? Wxo : Wxc;
            const float* bias = (g == 0) ? bi  : (g == 1) ? bf  : (g == 2) ? bo  : bc;

            {
                int b = t >> 2, part = t & 3;
                int tok = inputs[b * SS + s];
                const float4* src = (const float4*)(emb + (size_t)tok * EE) + part * 8;
                #pragma unroll
                for (int j = 0; j < 8; j++) {
                    float4 v = src[j];
                    int k = part * 32 + j * 4;
                    Xs[(k + 0) * BB + b] = v.x;
                    Xs[(k + 1) * BB + b] = v.y;
                    Xs[(k + 2) * BB + b] = v.z;
                    Xs[(k + 3) * BB + b] = v.w;
                }
            }
            __syncthreads();

            int cg = t & 15, bg = t >> 4;
            int b0 = bg * 4;
            const float* Wp = Wx + colg0 + cg * 4;
            float acc[4][4];
            #pragma unroll
            for (int j = 0; j < 4; j++) { acc[j][0]=0.f; acc[j][1]=0.f; acc[j][2]=0.f; acc[j][3]=0.f; }

            #pragma unroll 4
            for (int k = 0; k < EE; k++) {
                float4 wv = __ldg((const float4*)(Wp + (size_t)k * HH));
                float4 xv = *(const float4*)&Xs[k * BB + b0];
                float wa[4] = {wv.x, wv.y, wv.z, wv.w};
                float xa[4] = {xv.x, xv.y, xv.z, xv.w};
                #pragma unroll
                for (int j = 0; j < 4; j++)
                    #pragma unroll
                    for (int jj = 0; jj < 4; jj++)
                        acc[j][jj] = fmaf(wa[j], xa[jj], acc[j][jj]);
            }

            size_t base = ((size_t)s * GG + (size_t)g * HH + colg0 + cg * 4) * BB;
            #pragma unroll
            for (int j = 0; j < 4; j++) {
                float bv = bias[colg0 + cg * 4 + j];
                float4 v = make_float4(acc[j][0] + bv, acc[j][1] + bv, acc[j][2] + bv, acc[j][3] + bv);
                *(float4*)&g_xg[base + (size_t)j * BB + b0] = v;
            }

            __threadfence();
            __syncthreads();
            if (t == 0) red_release_add(&g_xgcnt[s >> 5], 1u);   // 1024 per 32-s block
        }
        return;
    }

    // ================= consumer path: R5-exact recurrence + R5 atomic barrier =
    float*  Gsm  = (float*)(sm + G_OFF);
    __half* HnSm = (__half*)(sm + HN_OFF);
    float*  Ysm  = (float*)(sm + YS_OFF);
    const uint32_t smb = smem_u32(sm);
    const uint32_t Ab  = smb;
    const uint32_t Bb  = smb + A_BYTES;
    const int hbase = cta * HPC;

    // load prebuilt A image (32 KB)
    {
        const float4* asrc = (const float4*)(g_Abuf + (size_t)cta * A_BYTES);
        float4* adst = (float4*)sm;
        #pragma unroll
        for (int j = 0; j < 8; j++)
            adst[j * 256 + t] = __ldg(&asrc[j * 256 + t]);
    }

    // ldmatrix lane-address precompute
    const int q = lane >> 3, r8 = lane & 7;
    const int mt = wid & 1;
    const int np = wid >> 1;
    const int arow = mt * 16 + r8 + ((q & 1) << 3);
    const uint32_t acol = (uint32_t)(q >> 1) * 16;
    const uint32_t aBase = Ab + (uint32_t)arow * 1024;
    const uint32_t axor  = ((uint32_t)arow & 7) << 4;
    const int brow = np * 16 + r8 + ((q >> 1) << 3);
    const uint32_t bcol = (uint32_t)(q & 1) * 16;
    const uint32_t bBase = Bb + (uint32_t)brow * 1024;
    const uint32_t bxor  = ((uint32_t)brow & 7) << 4;

    // epilogue role
    const int u = wid, eb = lane;
    float C0r = g_Cbuf[(hbase + u) * BB + eb];
    float C1r = g_Cbuf[(hbase + u) * BB + eb + 32];
    const float wef = g_weff[hbase + u];
    __syncthreads();

    for (int step = 0; step < SS; step++) {
        // wait for producers to finish this 32-step xg block (amortized)
        if ((step & 31) == 0) {
            if (t == 0) {
                while (ld_acquire(&g_xgcnt[step >> 5]) < 1024u) { }
            }
            __syncthreads();
        }

        // xg prefetch (8 scalar loads, coalesced; consumed after GEMM)
        size_t xb = ((size_t)step * GG + hbase + u) * BB + eb;
        float xi0 = __ldg(&g_xg[xb]),          xi1 = __ldg(&g_xg[xb + 32]);
        float xf0 = __ldg(&g_xg[xb + 32768]),  xf1 = __ldg(&g_xg[xb + 32768 + 32]);
        float xo0 = __ldg(&g_xg[xb + 65536]),  xo1 = __ldg(&g_xg[xb + 65536 + 32]);
        float xc0 = __ldg(&g_xg[xb + 98304]),  xc1 = __ldg(&g_xg[xb + 98304 + 32]);

        // stage H [b][h] fp16 -> Bsm, per-row XOR swizzle
        {
            const float4* hs = (const float4*)g_Hbuf[step & 1];
            #pragma unroll
            for (int j = 0; j < 16; j++) {
                int i16 = j * 256 + t;
                float4 v = __ldcg(&hs[i16]);
                uint32_t b   = (uint32_t)i16 >> 6;
                uint32_t c16 = (uint32_t)i16 & 63;
                *(float4*)(sm + A_BYTES + b * 1024 + ((c16 * 16) ^ ((b & 7) << 4))) = v;
            }
        }
        __syncthreads();

        // GEMM: per warp 32 k-slices, 2 ntiles
        float d0[4] = {0.f, 0.f, 0.f, 0.f};
        float d1[4] = {0.f, 0.f, 0.f, 0.f};
        #pragma unroll 8
        for (int ks = 0; ks < 32; ks++) {
            uint32_t a[4], b2[4];
            ldsm4(a,  aBase + (((uint32_t)ks * 32 + acol) ^ axor));
            ldsm4(b2, bBase + (((uint32_t)ks * 32 + bcol) ^ bxor));
            mma16816(d0, a, b2);
            mma16816(d1, a, b2 + 2);
        }
        {
            int g4 = lane >> 2, t4 = lane & 3;
            int mrow = mt * 16 + g4, nc = np * 16 + 2 * t4;
            *(float2*)&Gsm[mrow * 72 + nc]           = make_float2(d0[0], d0[1]);
            *(float2*)&Gsm[(mrow + 8) * 72 + nc]     = make_float2(d0[2], d0[3]);
            *(float2*)&Gsm[mrow * 72 + nc + 8]       = make_float2(d1[0], d1[1]);
            *(float2*)&Gsm[(mrow + 8) * 72 + nc + 8] = make_float2(d1[2], d1[3]);
        }
        __syncthreads();

        // epilogue: 2 cells per thread
        {
            float pi = xi0 + Gsm[( 0 + u) * 72 + eb];
            float pf = xf0 + Gsm[( 8 + u) * 72 + eb];
            float po = xo0 + Gsm[(16 + u) * 72 + eb];
            float pc = xc0 + Gsm[(24 + u) * 72 + eb];
            float I = sigf(pi), F = sigf(pf), O = sigf(po), Ct = tanhf_(pc);
            C0r = F * C0r + I * Ct;
            float Hn = O * tanhf_(C0r);
            HnSm[u * 66 + eb] = __float2half_rn(Hn);
            Ysm[u * 72 + eb]  = Hn * wef;
            if (step == SS - 1) { g_Hfin[(hbase + u) * BB + eb] = Hn; g_Cbuf[(hbase + u) * BB + eb] = C0r; }
        }
        {
            int bb = eb + 32;
            float pi = xi1 + Gsm[( 0 + u) * 72 + bb];
            float pf = xf1 + Gsm[( 8 + u) * 72 + bb];
            float po = xo1 + Gsm[(16 + u) * 72 + bb];
            float pc = xc1 + Gsm[(24 + u) * 72 + bb];
            float I = sigf(pi), F = sigf(pf), O = sigf(po), Ct = tanhf_(pc);
            C1r = F * C1r + I * Ct;
            float Hn = O * tanhf_(C1r);
            HnSm[u * 66 + bb] = __float2half_rn(Hn);
            Ysm[u * 72 + bb]  = Hn * wef;
            if (step == SS - 1) { g_Hfin[(hbase + u) * BB + bb] = Hn; g_Cbuf[(hbase + u) * BB + bb] = C1r; }
        }
        __syncthreads();

        // pack new H (coalesced 16B per batch) + Y partial
        if (t < BB) {
            uint32_t p[4];
            #pragma unroll
            for (int uu = 0; uu < 4; uu++) {
                uint32_t lo = (uint32_t)__half_as_ushort(HnSm[(2 * uu)     * 66 + t]);
                uint32_t hi = (uint32_t)__half_as_ushort(HnSm[(2 * uu + 1) * 66 + t]);
                p[uu] = lo | (hi << 16);
            }
            *(uint4*)((unsigned char*)g_Hbuf[(step + 1) & 1] + (size_t)t * 1024 + (size_t)cta * 16)
                = make_uint4(p[0], p[1], p[2], p[3]);
        } else if (t < 2 * BB) {
            int bb = t - BB;
            float y = 0.f;
            #pragma unroll
            for (int uu = 0; uu < 8; uu++) y += Ysm[uu * 72 + bb];
            g_party[((size_t)cta * SS + step) * BB + bb] = y;
        }

        // ---- R5-proven 64-CTA barrier: atomic arrival + atomic poll ----
        __threadfence();
        __syncthreads();
        if (t == 0) {
            atomicAdd(&g_bar[step], 1u);
            while (atomicAdd(&g_bar[step], 0u) < (unsigned)NCR) { }
            __threadfence();
        }
        __syncthreads();
    }
}

// ---------------- finalize ----------------------------------------------------
__global__ void __launch_bounds__(NTHR) fin_kernel(float* __restrict__ out, int out_size)
{
    int blk = blockIdx.x, t = threadIdx.x;
    if (blk < SS) {
        if (t < BB) {
            float y = g_beff[0];
            #pragma unroll
            for (int c = 0; c < NCR; c++)
                y += g_party[((size_t)c * SS + blk) * BB + t];
            int o = blk * BB + t;
            if (o < out_size) out[o] = y;
        }
    } else {
        if (out_size < SS * BB + 2 * HH * BB) return;
        int i = (blk - SS) * NTHR + t;
        if (i < HH * BB) {
            int h = i >> 6, b = i & 63;
            out[SS * BB + b * HH + h] = g_Hfin[i];
        } else {
            int j = i - HH * BB;
            int h = j >> 6, b = j & 63;
            out[SS * BB + HH * BB + b * HH + h] = g_Cbuf[j];
        }
    }
}

// ---------------- launch ------------------------------------------------------
extern "C" void kernel_launch(void* const* d_in, const int* in_sizes, int n_in,
                              void* d_out, int out_size)
{
    const int*   inputs = (const int*)d_in[0];
    const float* H0  = (const float*)d_in[1];
    const float* C0  = (const float*)d_in[2];
    const float* emb = (const float*)d_in[3];
    const float* Wxi = (const float*)d_in[4];
    const float* Whi = (const float*)d_in[5];
    const float* bi  = (const float*)d_in[6];
    const float* Wxf = (const float*)d_in[7];
    const float* Whf = (const float*)d_in[8];
    const float* bf  = (const float*)d_in[9];
    const float* Wxo = (const float*)d_in[10];
    const float* Who = (const float*)d_in[11];
    const float* bo  = (const float*)d_in[12];
    const float* Wxc = (const float*)d_in[13];
    const float* Whc = (const float*)d_in[14];
    const float* bc  = (const float*)d_in[15];
    const float* Whq = (const float*)d_in[16];
    const float* bq  = (const float*)d_in[17];
    const float* dw  = (const float*)d_in[18];
    const float* db  = (const float*)d_in[19];
    float* out = (float*)d_out;

    cudaFuncSetAttribute(rnn_kernel, cudaFuncAttributeMaxDynamicSharedMemorySize, RNN_SMEM);

    init_kernel<<<128, NTHR>>>(H0, C0, Whq, bq, dw, db);
    prep_kernel<<<(NCR * MRR * HH) / NTHR, NTHR>>>(Whi, Whf, Who, Whc);
    rnn_kernel<<<NCR + NPR, NTHR, RNN_SMEM>>>(inputs, emb,
                                              Wxi, Wxf, Wxo, Wxc, bi, bf, bo, bc);
    fin_kernel<<<SS + (2 * HH * BB) / NTHR, NTHR>>>(out, out_size);
}